// round 2
// baseline (speedup 1.0000x reference)
#include <cuda_runtime.h>

#define NN 20000
#define NE 400000
#define H  256

// ------- static scratch (allocations forbidden) -------
__device__ float    g_a[2][NN*H];
__device__ float    g_c[2][NN*H];
__device__ unsigned g_segout[2][NN*H];   // mapped-uint running max, 0 = empty
__device__ float    g_hcat[NN*2*H];      // [N,512]
__device__ float    g_xw[2][NN*128];
__device__ float    g_h2[NN*256];
__device__ int      g_deg[2][NN];
__device__ int      g_offs[2][NN+1];
__device__ int      g_cursor[2][NN];
__device__ int      g_ssrc[2][NE];
__device__ int      g_sdst[2][NE];
__device__ float    g_dinv[2][NN];
__device__ float    g_partial[1024*3];

__device__ __forceinline__ unsigned long long dup2(float x) {
    unsigned long long r;
    asm("mov.b64 %0, {%1, %1};" : "=l"(r) : "r"(__float_as_int(x)));
    return r;
}
__device__ __forceinline__ void fma2(unsigned long long& d, unsigned long long a,
                                     unsigned long long b) {
    asm("fma.rn.f32x2 %0, %1, %2, %0;" : "+l"(d) : "l"(a), "l"(b));
}
// order-preserving float->uint; every real float maps > 0 (sentinel)
__device__ __forceinline__ unsigned fmap(float f) {
    unsigned b = __float_as_uint(f);
    return b ^ ((unsigned)((int)b >> 31) | 0x80000000u);
}

__global__ void init_kernel() {
    int idx = blockIdx.x * 256 + threadIdx.x;
    if (idx < 2*NN*H) (&g_segout[0][0])[idx] = 0u;
    if (idx < 2*NN)   (&g_deg[0][0])[idx] = 0;
}

// fold 6->H layer: a = pos.(W1[0:3]+W1[3:6]) + b1 ; c = pos.W1[3:6]
__global__ void uv_kernel(const float* __restrict__ pos, const float* __restrict__ W1,
                          const float* __restrict__ bias1, int g) {
    int i = blockIdx.x, ch = threadIdx.x;
    float p0 = pos[i*3+0], p1 = pos[i*3+1], p2 = pos[i*3+2];
    float c = p0*W1[3*H+ch] + p1*W1[4*H+ch] + p2*W1[5*H+ch];
    float a = p0*W1[0*H+ch] + p1*W1[1*H+ch] + p2*W1[2*H+ch] + c + bias1[ch];
    g_a[g][i*H+ch] = a;
    g_c[g][i*H+ch] = c;
}

__global__ void deg_kernel(const int* __restrict__ ei, int g) {
    int e = blockIdx.x * 256 + threadIdx.x;
    if (e < NE) atomicAdd(&g_deg[g][ei[NE + e]], 1);
}

__global__ void scan_kernel(int g) {
    __shared__ int ss[1024];
    int t = threadIdx.x;
    const int CH = (NN + 1023) / 1024;
    int beg = t * CH, end = beg + CH;
    if (end > NN) end = NN;
    if (beg > NN) beg = NN;
    int s = 0;
    for (int i = beg; i < end; i++) s += g_deg[g][i];
    ss[t] = s;
    __syncthreads();
    for (int off = 1; off < 1024; off <<= 1) {
        int v = (t >= off) ? ss[t-off] : 0;
        __syncthreads();
        ss[t] += v;
        __syncthreads();
    }
    int run = (t == 0) ? 0 : ss[t-1];
    for (int i = beg; i < end; i++) {
        g_offs[g][i] = run; g_cursor[g][i] = run; run += g_deg[g][i];
    }
    if (t == 1023) g_offs[g][NN] = NE;
}

__global__ void dinv_kernel() {
    int idx = blockIdx.x * 256 + threadIdx.x;
    if (idx < 2*NN) {
        int g = idx / NN, i = idx - g*NN;
        g_dinv[g][i] = rsqrtf(1.f + (float)g_deg[g][i]);
    }
}

__global__ void fill_kernel(const int* __restrict__ ei, int g) {
    int e = blockIdx.x * 256 + threadIdx.x;
    if (e < NE) {
        int d = ei[NE + e];
        int p = atomicAdd(&g_cursor[g][d], 1);
        g_ssrc[g][p] = ei[e];
        g_sdst[g][p] = d;
    }
}

// 64 sorted edges x 256 channels per block; FFMA2 GEMM + fused segmented max
__global__ __launch_bounds__(256, 2)
void pointnet_kernel(const float* __restrict__ W2, const float* __restrict__ b2, int g) {
    __shared__ unsigned long long s_hid[64*16];  // [edge][k], value dup'd in both lanes
    __shared__ float4 s_w2[16*64];               // [k][256 ch]
    __shared__ int s_src[64], s_dst[64];
    const float* __restrict__ A = g_a[g];
    const float* __restrict__ C = g_c[g];
    unsigned* __restrict__ seg = &g_segout[g][0];
    int tid = threadIdx.x;
    int e0 = blockIdx.x * 64;
    if (tid < 64) { s_src[tid] = g_ssrc[g][e0+tid]; s_dst[tid] = g_sdst[g][e0+tid]; }
    __syncthreads();
    int tx = tid & 31, ty = tid >> 5;
    int le = tid >> 2, lk = (tid & 3) * 4;
    int lsrc = s_src[le] * H, ldst = s_dst[le] * H;

    unsigned long long acc[8][4];
#pragma unroll
    for (int i = 0; i < 8; i++)
#pragma unroll
        for (int p = 0; p < 4; p++) acc[i][p] = 0ull;

    const float4* W24 = (const float4*)W2;
    const unsigned long long* s_w2u = (const unsigned long long*)s_w2;

    for (int k0 = 0; k0 < H; k0 += 16) {
        float4 av = *(const float4*)(A + lsrc + k0 + lk);
        float4 cv = *(const float4*)(C + ldst + k0 + lk);
        float4 wv[4];
#pragma unroll
        for (int q = 0; q < 4; q++)
            wv[q] = W24[(k0 + (tid >> 6) + q*4) * 64 + (tid & 63)];
        __syncthreads();
        s_hid[le*16 + lk + 0] = dup2(fmaxf(av.x - cv.x, 0.f));
        s_hid[le*16 + lk + 1] = dup2(fmaxf(av.y - cv.y, 0.f));
        s_hid[le*16 + lk + 2] = dup2(fmaxf(av.z - cv.z, 0.f));
        s_hid[le*16 + lk + 3] = dup2(fmaxf(av.w - cv.w, 0.f));
#pragma unroll
        for (int q = 0; q < 4; q++) s_w2[tid + q*256] = wv[q];
        __syncthreads();
#pragma unroll
        for (int kk = 0; kk < 16; kk++) {
            unsigned long long w[4];
#pragma unroll
            for (int p = 0; p < 4; p++) w[p] = s_w2u[kk*128 + tx + 32*p];
#pragma unroll
            for (int i = 0; i < 8; i++) {
                unsigned long long h = s_hid[(ty*8 + i)*16 + kk];
#pragma unroll
                for (int p = 0; p < 4; p++) fma2(acc[i][p], h, w[p]);
            }
        }
    }

    float2 bp[4];
#pragma unroll
    for (int p = 0; p < 4; p++) bp[p] = *(const float2*)(b2 + 2*tx + 64*p);
    float mx[8];
    int cur = -1;
#pragma unroll
    for (int i = 0; i < 8; i++) {
        int d = s_dst[ty*8 + i];
        float v[8];
#pragma unroll
        for (int p = 0; p < 4; p++) {
            v[2*p]   = __uint_as_float((unsigned)(acc[i][p] & 0xffffffffull)) + bp[p].x;
            v[2*p+1] = __uint_as_float((unsigned)(acc[i][p] >> 32))           + bp[p].y;
        }
        if (d != cur) {
            if (cur >= 0)
#pragma unroll
                for (int p = 0; p < 4; p++) {
                    atomicMax(&seg[cur*H + 2*tx + 64*p],     fmap(mx[2*p]));
                    atomicMax(&seg[cur*H + 2*tx + 64*p + 1], fmap(mx[2*p+1]));
                }
            cur = d;
#pragma unroll
            for (int q = 0; q < 8; q++) mx[q] = v[q];
        } else {
#pragma unroll
            for (int q = 0; q < 8; q++) mx[q] = fmaxf(mx[q], v[q]);
        }
    }
#pragma unroll
    for (int p = 0; p < 4; p++) {
        atomicMax(&seg[cur*H + 2*tx + 64*p],     fmap(mx[2*p]));
        atomicMax(&seg[cur*H + 2*tx + 64*p + 1], fmap(mx[2*p+1]));
    }
}

// decode mapped max -> relu'd hcat (u<=0x80000000 means empty or <=0 -> 0)
__global__ void decode_kernel() {
    int idx = blockIdx.x * 256 + threadIdx.x;
    if (idx >= 2*NN*H) return;
    int g = idx / (NN*H), rem = idx - g*(NN*H);
    unsigned u = (&g_segout[0][0])[idx];
    float f = (u > 0x80000000u) ? __uint_as_float(u ^ 0x80000000u) : 0.f;
    g_hcat[(rem >> 8)*512 + g*256 + (rem & 255)] = f;
}

// xw = hcat @ gW : [N,512]@[512,128]
__global__ __launch_bounds__(256)
void xw_kernel(const float* __restrict__ Wg, int g) {
    __shared__ float s_a[64*16];
    __shared__ float4 s_b[16*32];
    int tid = threadIdx.x, tx = tid & 31, ty = tid >> 5;
    int row0 = blockIdx.x * 64;
    float acc[8][4];
#pragma unroll
    for (int i = 0; i < 8; i++)
#pragma unroll
        for (int j = 0; j < 4; j++) acc[i][j] = 0.f;
    int lr = tid >> 2, lk = (tid & 3) * 4;
    int ar = row0 + lr; if (ar > NN-1) ar = NN-1;
    const float4* B4 = (const float4*)Wg;
    for (int k0 = 0; k0 < 512; k0 += 16) {
        float4 av = *(const float4*)(g_hcat + ar*512 + k0 + lk);
        float4 bv[2];
#pragma unroll
        for (int q = 0; q < 2; q++) {
            int idx = tid + q*256;
            bv[q] = B4[(k0 + (idx >> 5))*32 + (idx & 31)];
        }
        __syncthreads();
        *(float4*)(s_a + lr*16 + lk) = av;
#pragma unroll
        for (int q = 0; q < 2; q++) s_b[tid + q*256] = bv[q];
        __syncthreads();
#pragma unroll
        for (int kk = 0; kk < 16; kk++) {
            float4 b = s_b[kk*32 + tx];
#pragma unroll
            for (int i = 0; i < 8; i++) {
                float a = s_a[(ty*8 + i)*16 + kk];
                acc[i][0] += a*b.x; acc[i][1] += a*b.y;
                acc[i][2] += a*b.z; acc[i][3] += a*b.w;
            }
        }
    }
#pragma unroll
    for (int i = 0; i < 8; i++) {
        int r = row0 + ty*8 + i;
        if (r < NN)
            *(float4*)(g_xw[g] + r*128 + tx*4) =
                make_float4(acc[i][0], acc[i][1], acc[i][2], acc[i][3]);
    }
}

// GCN aggregation: deterministic CSR sum + self loop + bias + relu
__global__ void agg_kernel(const float* __restrict__ bias, int g) {
    int i = blockIdx.x, ch = threadIdx.x;
    const float* __restrict__ xw = g_xw[g];
    float di = g_dinv[g][i];
    int beg = g_offs[g][i], end = g_offs[g][i+1];
    float acc = 0.f;
    for (int e = beg; e < end; e++) {
        int s = g_ssrc[g][e];
        acc += xw[s*128 + ch] * g_dinv[g][s];
    }
    float v = di*acc + xw[i*128 + ch]*di*di + bias[ch];
    g_h2[i*256 + g*128 + ch] = fmaxf(v, 0.f);
}

// c3 GEMM [N,256]@[256,128] + relu + fused classifier partial dot
__global__ __launch_bounds__(256)
void c3cls_kernel(const float* __restrict__ Wc, const float* __restrict__ bc,
                  const float* __restrict__ clsW) {
    __shared__ float s_a[64*16];
    __shared__ float4 s_b[16*32];
    __shared__ float red[256];
    int tid = threadIdx.x, tx = tid & 31, ty = tid >> 5;
    int row0 = blockIdx.x * 64;
    float acc[8][4];
#pragma unroll
    for (int i = 0; i < 8; i++)
#pragma unroll
        for (int j = 0; j < 4; j++) acc[i][j] = 0.f;
    int lr = tid >> 2, lk = (tid & 3) * 4;
    int ar = row0 + lr; if (ar > NN-1) ar = NN-1;
    const float4* B4 = (const float4*)Wc;
    for (int k0 = 0; k0 < 256; k0 += 16) {
        float4 av = *(const float4*)(g_h2 + ar*256 + k0 + lk);
        float4 bv[2];
#pragma unroll
        for (int q = 0; q < 2; q++) {
            int idx = tid + q*256;
            bv[q] = B4[(k0 + (idx >> 5))*32 + (idx & 31)];
        }
        __syncthreads();
        *(float4*)(s_a + lr*16 + lk) = av;
#pragma unroll
        for (int q = 0; q < 2; q++) s_b[tid + q*256] = bv[q];
        __syncthreads();
#pragma unroll
        for (int kk = 0; kk < 16; kk++) {
            float4 b = s_b[kk*32 + tx];
#pragma unroll
            for (int i = 0; i < 8; i++) {
                float a = s_a[(ty*8 + i)*16 + kk];
                acc[i][0] += a*b.x; acc[i][1] += a*b.y;
                acc[i][2] += a*b.z; acc[i][3] += a*b.w;
            }
        }
    }
    float sum0 = 0.f, sum1 = 0.f, sum2 = 0.f;
#pragma unroll
    for (int i = 0; i < 8; i++) {
        int r = row0 + ty*8 + i;
        if (r < NN) {
#pragma unroll
            for (int jj = 0; jj < 4; jj++) {
                float v = fmaxf(acc[i][jj] + bc[tx*4 + jj], 0.f);
                const float* w = clsW + (r*128 + tx*4 + jj)*3;
                sum0 += v*w[0]; sum1 += v*w[1]; sum2 += v*w[2];
            }
        }
    }
    float sums[3] = {sum0, sum1, sum2};
#pragma unroll
    for (int r3 = 0; r3 < 3; r3++) {
        red[tid] = sums[r3];
        __syncthreads();
        for (int s = 128; s > 0; s >>= 1) {
            if (tid < s) red[tid] += red[tid + s];
            __syncthreads();
        }
        if (tid == 0) g_partial[blockIdx.x*3 + r3] = red[0];
        __syncthreads();
    }
}

__global__ void final_kernel(const float* __restrict__ clsb, float* __restrict__ out, int nblk) {
    int r = threadIdx.x;
    if (r < 3) {
        double s = (double)clsb[r];
        for (int i = 0; i < nblk; i++) s += (double)g_partial[i*3 + r];
        out[r] = (float)s;
    }
}

extern "C" void kernel_launch(void* const* d_in, const int* in_sizes, int n_in,
                              void* d_out, int out_size) {
    const float *pos[2]={0,0}, *W1[2]={0,0}, *b1[2]={0,0}, *W2[2]={0,0}, *b2[2]={0,0};
    const float *gW[2]={0,0}, *gb[2]={0,0}, *cW=0, *cb=0, *clsW=0, *clsb=0;
    const int *ei[2]={0,0};
    int npos=0, nei=0, nw1=0, n256=0, n64k=0, n128=0;
    for (int i = 0; i < n_in; i++) {
        int sz = in_sizes[i];
        const float* f = (const float*)d_in[i];
        if (sz == 3*NN)            { if (npos<2) pos[npos++] = f; }
        else if (sz == 2*NE)       { if (nei<2)  ei[nei++] = (const int*)d_in[i]; }
        else if (sz == 6*H)        { if (nw1<2)  W1[nw1++] = f; }
        else if (sz == H)          { int j=n256++; if(j==0)b1[0]=f; else if(j==1)b2[0]=f;
                                     else if(j==2)b1[1]=f; else if(j==3)b2[1]=f; }
        else if (sz == H*H)        { int j=n64k++; if(j<2) W2[j]=f; else if(j<4) gW[j-2]=f; }
        else if (sz == H/2)        { int j=n128++; if(j<2) gb[j]=f; else cb=f; }
        else if (sz == H*(H/2))    { cW = f; }
        else if (sz == NN*(H/2)*3) { clsW = f; }
        else if (sz == 3)          { clsb = f; }
        // size NN (batch_0/batch_1): unused (single graph per batch)
    }

    init_kernel<<<(2*NN*H + 255)/256, 256>>>();
    for (int g = 0; g < 2; g++) {
        uv_kernel<<<NN, 256>>>(pos[g], W1[g], b1[g], g);
        deg_kernel<<<(NE + 255)/256, 256>>>(ei[g], g);
    }
    for (int g = 0; g < 2; g++) {
        scan_kernel<<<1, 1024>>>(g);
        fill_kernel<<<(NE + 255)/256, 256>>>(ei[g], g);
    }
    dinv_kernel<<<(2*NN + 255)/256, 256>>>();
    for (int g = 0; g < 2; g++)
        pointnet_kernel<<<NE/64, 256>>>(W2[g], b2[g], g);
    decode_kernel<<<(2*NN*H + 255)/256, 256>>>();
    for (int g = 0; g < 2; g++)
        xw_kernel<<<(NN + 63)/64, 256>>>(gW[g], g);
    for (int g = 0; g < 2; g++)
        agg_kernel<<<NN, 128>>>(gb[g], g);
    int nblk = (NN + 63)/64;
    c3cls_kernel<<<nblk, 256>>>(cW, cb, clsW);
    final_kernel<<<1, 32>>>(clsb, (float*)d_out, nblk);
}

// round 4
// speedup vs baseline: 1.7032x; 1.7032x over previous
#include <cuda_runtime.h>
#include <cuda_bf16.h>
#include <cstdint>

#define NN 20000
#define NE 400000
#define H  256

// ------- static scratch (allocations forbidden) -------
__device__ float    g_a[2][NN*H];
__device__ float    g_c[2][NN*H];
__device__ unsigned g_segout[2][NN*H];   // mapped-uint running max, 0 = empty
__device__ float    g_hcat[NN*2*H];
__device__ float    g_xw[2][NN*128];
__device__ float    g_h2[NN*256];
__device__ int      g_deg[2][NN];
__device__ int      g_offs[2][NN+1];
__device__ int      g_cursor[2][NN];
__device__ int      g_ssrc[2][NE];
__device__ int      g_sdst[2][NE];
__device__ float    g_dinv[2][NN];
__device__ float    g_partial[1024*3];
__device__ unsigned short g_w2h[2][H*H]; // bf16 hi, layout [chunk][n][64k]
__device__ unsigned short g_w2l[2][H*H]; // bf16 lo

__device__ __forceinline__ unsigned fmap(float f) {
    unsigned b = __float_as_uint(f);
    return b ^ ((unsigned)((int)b >> 31) | 0x80000000u);
}
__device__ __forceinline__ void mma_bf16(float* c, uint32_t a0, uint32_t a1,
                                         uint32_t a2, uint32_t a3,
                                         uint32_t b0, uint32_t b1) {
    asm volatile(
        "mma.sync.aligned.m16n8k16.row.col.f32.bf16.bf16.f32 "
        "{%0,%1,%2,%3}, {%4,%5,%6,%7}, {%8,%9}, {%0,%1,%2,%3};"
        : "+f"(c[0]), "+f"(c[1]), "+f"(c[2]), "+f"(c[3])
        : "r"(a0), "r"(a1), "r"(a2), "r"(a3), "r"(b0), "r"(b1));
}

// ------- small prep kernels -------
__global__ void init_kernel() {
    int idx = blockIdx.x * 256 + threadIdx.x;
    if (idx < 2*NN*H) (&g_segout[0][0])[idx] = 0u;
    if (idx < 2*NN)   (&g_deg[0][0])[idx] = 0;
}

__global__ void uv_kernel(const float* __restrict__ pos, const float* __restrict__ W1,
                          const float* __restrict__ bias1, int g) {
    int i = blockIdx.x, ch = threadIdx.x;
    float p0 = pos[i*3+0], p1 = pos[i*3+1], p2 = pos[i*3+2];
    float c = p0*W1[3*H+ch] + p1*W1[4*H+ch] + p2*W1[5*H+ch];
    float a = p0*W1[0*H+ch] + p1*W1[1*H+ch] + p2*W1[2*H+ch] + c + bias1[ch];
    g_a[g][i*H+ch] = a;
    g_c[g][i*H+ch] = c;
}

// W2 bf16 split, transposed to [n][k], chunked over k by 64
__global__ void w2prep_kernel(const float* __restrict__ W2, int g) {
    int idx = blockIdx.x * 256 + threadIdx.x;  // k*256+n
    int k = idx >> 8, n = idx & 255;
    float w = W2[idx];
    __nv_bfloat16 hb = __float2bfloat16(w);
    float hf = __bfloat162float(hb);
    __nv_bfloat16 lb = __float2bfloat16(w - hf);
    int o = (k >> 6)*16384 + n*64 + (k & 63);
    g_w2h[g][o] = *(unsigned short*)&hb;
    g_w2l[g][o] = *(unsigned short*)&lb;
}

__global__ void deg_kernel(const int* __restrict__ ei, int g) {
    int e = blockIdx.x * 256 + threadIdx.x;
    if (e < NE) atomicAdd(&g_deg[g][ei[NE + e]], 1);
}

__global__ void scan_kernel(int g) {
    __shared__ int ss[1024];
    int t = threadIdx.x;
    const int CH = (NN + 1023) / 1024;
    int beg = t * CH, end = beg + CH;
    if (end > NN) end = NN;
    if (beg > NN) beg = NN;
    int s = 0;
    for (int i = beg; i < end; i++) s += g_deg[g][i];
    ss[t] = s;
    __syncthreads();
    for (int off = 1; off < 1024; off <<= 1) {
        int v = (t >= off) ? ss[t-off] : 0;
        __syncthreads();
        ss[t] += v;
        __syncthreads();
    }
    int run = (t == 0) ? 0 : ss[t-1];
    for (int i = beg; i < end; i++) {
        g_offs[g][i] = run; g_cursor[g][i] = run; run += g_deg[g][i];
    }
    if (t == 1023) g_offs[g][NN] = NE;
}

__global__ void dinv_kernel() {
    int idx = blockIdx.x * 256 + threadIdx.x;
    if (idx < 2*NN) {
        int g = idx / NN, i = idx - g*NN;
        g_dinv[g][i] = rsqrtf(1.f + (float)g_deg[g][i]);
    }
}

__global__ void fill_kernel(const int* __restrict__ ei, int g) {
    int e = blockIdx.x * 256 + threadIdx.x;
    if (e < NE) {
        int d = ei[NE + e];
        int p = atomicAdd(&g_cursor[g][d], 1);
        g_ssrc[g][p] = ei[e];
        g_sdst[g][p] = d;
    }
}

// ------- mma.sync pointnet: 128 sorted edges x 256 ch per block -------
// SMEM layout (bytes): rows padded to HP=72 halves (144B)
#define HP 72
#define OFF_HH 0
#define OFF_HL 18432
#define OFF_WH 36864
#define OFF_WL 73728
#define OFF_DST 131584
#define PN_SMEM 132096

__global__ __launch_bounds__(512, 1)
void pointnet_mma(const float* __restrict__ b2, int g) {
    extern __shared__ char AB[];
    int tid = threadIdx.x, lane = tid & 31, wid = tid >> 5;
    int e0 = blockIdx.x * 128;
    int* s_dst = (int*)(AB + OFF_DST);
    if (tid < 128) s_dst[tid] = g_sdst[g][e0 + tid];

    // per-thread gather assignment: edge = tid>>2, k quarter = (tid&3)*16
    int ge = tid >> 2, kq = (tid & 3) * 16;
    int esrc = g_ssrc[g][e0 + ge] * 256;
    int edst = g_sdst[g][e0 + ge] * 256;
    const float* __restrict__ Aa = g_a[g];
    const float* __restrict__ Cc = g_c[g];

    // warp tiling: 4 edge-groups x 4 ch-groups
    int eg = wid >> 2, cg = wid & 3;
    int qrow = lane >> 2;          // 0..7
    int qc = (lane & 3) * 2;       // 0,2,4,6

    float acc[2][8][4];
#pragma unroll
    for (int mt = 0; mt < 2; mt++)
#pragma unroll
        for (int nt = 0; nt < 8; nt++)
#pragma unroll
            for (int j = 0; j < 4; j++) acc[mt][nt][j] = 0.f;

    for (int ck = 0; ck < 4; ck++) {
        // ---- gather + bf16 split into s_hh/s_hl ----
        {
            int k0 = ck*64 + kq;
            float4 av[4], cv[4];
#pragma unroll
            for (int q = 0; q < 4; q++) {
                av[q] = *(const float4*)(Aa + esrc + k0 + q*4);
                cv[q] = *(const float4*)(Cc + edst + k0 + q*4);
            }
            char* ph = AB + OFF_HH + ge*144 + kq*2;
            char* pl = AB + OFF_HL + ge*144 + kq*2;
#pragma unroll
            for (int q = 0; q < 4; q++) {
                float h0 = fmaxf(av[q].x - cv[q].x, 0.f);
                float h1 = fmaxf(av[q].y - cv[q].y, 0.f);
                float h2 = fmaxf(av[q].z - cv[q].z, 0.f);
                float h3 = fmaxf(av[q].w - cv[q].w, 0.f);
                uint32_t hi0, hi1, lo0, lo1;
                asm("cvt.rn.bf16x2.f32 %0, %1, %2;" : "=r"(hi0) : "f"(h1), "f"(h0));
                asm("cvt.rn.bf16x2.f32 %0, %1, %2;" : "=r"(hi1) : "f"(h3), "f"(h2));
                float r0 = h0 - __uint_as_float(hi0 << 16);
                float r1 = h1 - __uint_as_float(hi0 & 0xffff0000u);
                float r2 = h2 - __uint_as_float(hi1 << 16);
                float r3 = h3 - __uint_as_float(hi1 & 0xffff0000u);
                asm("cvt.rn.bf16x2.f32 %0, %1, %2;" : "=r"(lo0) : "f"(r1), "f"(r0));
                asm("cvt.rn.bf16x2.f32 %0, %1, %2;" : "=r"(lo1) : "f"(r3), "f"(r2));
                *(uint32_t*)(ph + q*8)     = hi0;
                *(uint32_t*)(ph + q*8 + 4) = hi1;
                *(uint32_t*)(pl + q*8)     = lo0;
                *(uint32_t*)(pl + q*8 + 4) = lo1;
            }
        }
        // ---- stream W chunk [n][64] into s_wh/s_wl ----
        {
            const uint4* gh4 = (const uint4*)(g_w2h[g] + ck*16384);
            const uint4* gl4 = (const uint4*)(g_w2l[g] + ck*16384);
#pragma unroll
            for (int i = 0; i < 4; i++) {
                int idx = tid + i*512;
                int row = idx >> 3, q = idx & 7;
                *(uint4*)(AB + OFF_WH + row*144 + q*16) = gh4[idx];
                *(uint4*)(AB + OFF_WL + row*144 + q*16) = gl4[idx];
            }
        }
        __syncthreads();

        // ---- MMA over 4 k-steps of 16 ----
#pragma unroll
        for (int kk = 0; kk < 4; kk++) {
            int kb = kk*16 + qc;
            uint32_t ahh[2][2], ahl[2][2];
#pragma unroll
            for (int mt = 0; mt < 2; mt++) {
                int row = eg*32 + mt*16 + qrow;
                const char* ph = AB + OFF_HH + row*144 + kb*2;
                const char* pl = AB + OFF_HL + row*144 + kb*2;
                ahh[mt][0] = *(const uint32_t*)ph;
                ahh[mt][1] = *(const uint32_t*)(ph + 16);
                uint32_t ahh2 = *(const uint32_t*)(ph + 8*144);
                uint32_t ahh3 = *(const uint32_t*)(ph + 8*144 + 16);
                ahl[mt][0] = *(const uint32_t*)pl;
                ahl[mt][1] = *(const uint32_t*)(pl + 16);
                uint32_t ahl2 = *(const uint32_t*)(pl + 8*144);
                uint32_t ahl3 = *(const uint32_t*)(pl + 8*144 + 16);
#pragma unroll
                for (int nt = 0; nt < 8; nt++) {
                    int n = cg*64 + nt*8 + qrow;
                    const char* pw = AB + OFF_WH + n*144 + kb*2;
                    const char* pv = AB + OFF_WL + n*144 + kb*2;
                    uint32_t bh0 = *(const uint32_t*)pw;
                    uint32_t bh1 = *(const uint32_t*)(pw + 16);
                    uint32_t bl0 = *(const uint32_t*)pv;
                    uint32_t bl1 = *(const uint32_t*)(pv + 16);
                    mma_bf16(acc[mt][nt], ahh[mt][0], ahh2, ahh[mt][1], ahh3, bh0, bh1);
                    mma_bf16(acc[mt][nt], ahl[mt][0], ahl2, ahl[mt][1], ahl3, bh0, bh1);
                    mma_bf16(acc[mt][nt], ahh[mt][0], ahh2, ahh[mt][1], ahh3, bl0, bl1);
                }
            }
        }
        __syncthreads();
    }

    // ---- epilogue: accum -> SMEM buf[128][257] -> segmented max -> atomics ----
    float* buf = (float*)AB;
#pragma unroll
    for (int mt = 0; mt < 2; mt++) {
        int row = eg*32 + mt*16 + qrow;
#pragma unroll
        for (int nt = 0; nt < 8; nt++) {
            int col = cg*64 + nt*8 + qc;
            buf[row*257 + col]       = acc[mt][nt][0];
            buf[row*257 + col + 1]   = acc[mt][nt][1];
            buf[(row+8)*257 + col]   = acc[mt][nt][2];
            buf[(row+8)*257 + col+1] = acc[mt][nt][3];
        }
    }
    __syncthreads();
    {
        unsigned* __restrict__ seg = &g_segout[g][0];
        int gch = tid & 255;
        int ebase = (tid >> 8) * 64;
        float bias = b2[gch];
        int cur = s_dst[ebase];
        float mx = buf[ebase*257 + gch];
        for (int q = 1; q < 64; q++) {
            int d = s_dst[ebase + q];
            float v = buf[(ebase+q)*257 + gch];
            if (d != cur) {
                atomicMax(&seg[cur*256 + gch], fmap(mx + bias));
                cur = d; mx = v;
            } else mx = fmaxf(mx, v);
        }
        atomicMax(&seg[cur*256 + gch], fmap(mx + bias));
    }
}

// ------- remaining pipeline (unchanged from passing R1) -------
__global__ void decode_kernel() {
    int idx = blockIdx.x * 256 + threadIdx.x;
    if (idx >= 2*NN*H) return;
    int g = idx / (NN*H), rem = idx - g*(NN*H);
    unsigned u = (&g_segout[0][0])[idx];
    float f = (u > 0x80000000u) ? __uint_as_float(u ^ 0x80000000u) : 0.f;
    g_hcat[(rem >> 8)*512 + g*256 + (rem & 255)] = f;
}

__global__ __launch_bounds__(256)
void xw_kernel(const float* __restrict__ Wg, int g) {
    __shared__ float s_a[64*16];
    __shared__ float4 s_b[16*32];
    int tid = threadIdx.x, tx = tid & 31, ty = tid >> 5;
    int row0 = blockIdx.x * 64;
    float acc[8][4];
#pragma unroll
    for (int i = 0; i < 8; i++)
#pragma unroll
        for (int j = 0; j < 4; j++) acc[i][j] = 0.f;
    int lr = tid >> 2, lk = (tid & 3) * 4;
    int ar = row0 + lr; if (ar > NN-1) ar = NN-1;
    const float4* B4 = (const float4*)Wg;
    for (int k0 = 0; k0 < 512; k0 += 16) {
        float4 av = *(const float4*)(g_hcat + ar*512 + k0 + lk);
        float4 bv[2];
#pragma unroll
        for (int q = 0; q < 2; q++) {
            int idx = tid + q*256;
            bv[q] = B4[(k0 + (idx >> 5))*32 + (idx & 31)];
        }
        __syncthreads();
        *(float4*)(s_a + lr*16 + lk) = av;
#pragma unroll
        for (int q = 0; q < 2; q++) s_b[tid + q*256] = bv[q];
        __syncthreads();
#pragma unroll
        for (int kk = 0; kk < 16; kk++) {
            float4 b = s_b[kk*32 + tx];
#pragma unroll
            for (int i = 0; i < 8; i++) {
                float a = s_a[(ty*8 + i)*16 + kk];
                acc[i][0] += a*b.x; acc[i][1] += a*b.y;
                acc[i][2] += a*b.z; acc[i][3] += a*b.w;
            }
        }
    }
#pragma unroll
    for (int i = 0; i < 8; i++) {
        int r = row0 + ty*8 + i;
        if (r < NN)
            *(float4*)(g_xw[g] + r*128 + tx*4) =
                make_float4(acc[i][0], acc[i][1], acc[i][2], acc[i][3]);
    }
}

__global__ void agg_kernel(const float* __restrict__ bias, int g) {
    int i = blockIdx.x, ch = threadIdx.x;
    const float* __restrict__ xw = g_xw[g];
    float di = g_dinv[g][i];
    int beg = g_offs[g][i], end = g_offs[g][i+1];
    float acc = 0.f;
    for (int e = beg; e < end; e++) {
        int s = g_ssrc[g][e];
        acc += xw[s*128 + ch] * g_dinv[g][s];
    }
    float v = di*acc + xw[i*128 + ch]*di*di + bias[ch];
    g_h2[i*256 + g*128 + ch] = fmaxf(v, 0.f);
}

__global__ __launch_bounds__(256)
void c3cls_kernel(const float* __restrict__ Wc, const float* __restrict__ bc,
                  const float* __restrict__ clsW) {
    __shared__ float s_a[64*16];
    __shared__ float4 s_b[16*32];
    __shared__ float red[256];
    int tid = threadIdx.x, tx = tid & 31, ty = tid >> 5;
    int row0 = blockIdx.x * 64;
    float acc[8][4];
#pragma unroll
    for (int i = 0; i < 8; i++)
#pragma unroll
        for (int j = 0; j < 4; j++) acc[i][j] = 0.f;
    int lr = tid >> 2, lk = (tid & 3) * 4;
    int ar = row0 + lr; if (ar > NN-1) ar = NN-1;
    const float4* B4 = (const float4*)Wc;
    for (int k0 = 0; k0 < 256; k0 += 16) {
        float4 av = *(const float4*)(g_h2 + ar*256 + k0 + lk);
        float4 bv[2];
#pragma unroll
        for (int q = 0; q < 2; q++) {
            int idx = tid + q*256;
            bv[q] = B4[(k0 + (idx >> 5))*32 + (idx & 31)];
        }
        __syncthreads();
        *(float4*)(s_a + lr*16 + lk) = av;
#pragma unroll
        for (int q = 0; q < 2; q++) s_b[tid + q*256] = bv[q];
        __syncthreads();
#pragma unroll
        for (int kk = 0; kk < 16; kk++) {
            float4 b = s_b[kk*32 + tx];
#pragma unroll
            for (int i = 0; i < 8; i++) {
                float a = s_a[(ty*8 + i)*16 + kk];
                acc[i][0] += a*b.x; acc[i][1] += a*b.y;
                acc[i][2] += a*b.z; acc[i][3] += a*b.w;
            }
        }
    }
    float sum0 = 0.f, sum1 = 0.f, sum2 = 0.f;
#pragma unroll
    for (int i = 0; i < 8; i++) {
        int r = row0 + ty*8 + i;
        if (r < NN) {
#pragma unroll
            for (int jj = 0; jj < 4; jj++) {
                float v = fmaxf(acc[i][jj] + bc[tx*4 + jj], 0.f);
                const float* w = clsW + (r*128 + tx*4 + jj)*3;
                sum0 += v*w[0]; sum1 += v*w[1]; sum2 += v*w[2];
            }
        }
    }
    float sums[3] = {sum0, sum1, sum2};
#pragma unroll
    for (int r3 = 0; r3 < 3; r3++) {
        red[tid] = sums[r3];
        __syncthreads();
        for (int s = 128; s > 0; s >>= 1) {
            if (tid < s) red[tid] += red[tid + s];
            __syncthreads();
        }
        if (tid == 0) g_partial[blockIdx.x*3 + r3] = red[0];
        __syncthreads();
    }
}

__global__ void final_kernel(const float* __restrict__ clsb, float* __restrict__ out, int nblk) {
    int r = threadIdx.x;
    if (r < 3) {
        double s = (double)clsb[r];
        for (int i = 0; i < nblk; i++) s += (double)g_partial[i*3 + r];
        out[r] = (float)s;
    }
}

extern "C" void kernel_launch(void* const* d_in, const int* in_sizes, int n_in,
                              void* d_out, int out_size) {
    const float *pos[2]={0,0}, *W1[2]={0,0}, *b1[2]={0,0}, *W2[2]={0,0}, *b2[2]={0,0};
    const float *gW[2]={0,0}, *gb[2]={0,0}, *cW=0, *cb=0, *clsW=0, *clsb=0;
    const int *ei[2]={0,0};
    int npos=0, nei=0, nw1=0, n256=0, n64k=0, n128=0;
    for (int i = 0; i < n_in; i++) {
        int sz = in_sizes[i];
        const float* f = (const float*)d_in[i];
        if (sz == 3*NN)            { if (npos<2) pos[npos++] = f; }
        else if (sz == 2*NE)       { if (nei<2)  ei[nei++] = (const int*)d_in[i]; }
        else if (sz == 6*H)        { if (nw1<2)  W1[nw1++] = f; }
        else if (sz == H)          { int j=n256++; if(j==0)b1[0]=f; else if(j==1)b2[0]=f;
                                     else if(j==2)b1[1]=f; else if(j==3)b2[1]=f; }
        else if (sz == H*H)        { int j=n64k++; if(j<2) W2[j]=f; else if(j<4) gW[j-2]=f; }
        else if (sz == H/2)        { int j=n128++; if(j<2) gb[j]=f; else cb=f; }
        else if (sz == H*(H/2))    { cW = f; }
        else if (sz == NN*(H/2)*3) { clsW = f; }
        else if (sz == 3)          { clsb = f; }
    }

    static bool attr_done = false;
    if (!attr_done) {
        cudaFuncSetAttribute(pointnet_mma, cudaFuncAttributeMaxDynamicSharedMemorySize, PN_SMEM);
        attr_done = true;
    }

    init_kernel<<<(2*NN*H + 255)/256, 256>>>();
    for (int g = 0; g < 2; g++) {
        uv_kernel<<<NN, 256>>>(pos[g], W1[g], b1[g], g);
        w2prep_kernel<<<H*H/256, 256>>>(W2[g], g);
        deg_kernel<<<(NE + 255)/256, 256>>>(ei[g], g);
    }
    for (int g = 0; g < 2; g++) {
        scan_kernel<<<1, 1024>>>(g);
        fill_kernel<<<(NE + 255)/256, 256>>>(ei[g], g);
    }
    dinv_kernel<<<(2*NN + 255)/256, 256>>>();
    for (int g = 0; g < 2; g++)
        pointnet_mma<<<NE/128, 512, PN_SMEM>>>(b2[g], g);
    decode_kernel<<<(2*NN*H + 255)/256, 256>>>();
    for (int g = 0; g < 2; g++)
        xw_kernel<<<(NN + 63)/64, 256>>>(gW[g], g);
    for (int g = 0; g < 2; g++)
        agg_kernel<<<NN, 128>>>(gb[g], g);
    int nblk = (NN + 63)/64;
    c3cls_kernel<<<nblk, 256>>>(cW, cb, clsW);
    final_kernel<<<1, 32>>>(clsb, (float*)d_out, nblk);
}

// round 6
// speedup vs baseline: 1.7590x; 1.0328x over previous
#include <cuda_runtime.h>
#include <cuda_bf16.h>
#include <cstdint>

#define NN 20000
#define NE 400000
#define H  256

// ------- static scratch (allocations forbidden) -------
__device__ float    g_a[2][NN*H];
__device__ float    g_c[2][NN*H];
__device__ unsigned g_segout[2][NN*H];   // mapped-uint running max, 0 = empty
__device__ float    g_hcat[NN*2*H];
__device__ float    g_xw[2][NN*128];
__device__ float    g_h2[NN*256];
__device__ int      g_deg[2][NN];
__device__ int      g_offs[2][NN+1];
__device__ int      g_cursor[2][NN];
__device__ int      g_ssrc[2][NE];
__device__ int      g_sdst[2][NE];
__device__ float    g_dinv[2][NN];
__device__ float    g_partial[1024*3];
__device__ unsigned short g_w2h[2][H*H]; // bf16 hi of W2^T, [chunk][n][64k]
__device__ unsigned short g_w2l[2][H*H]; // bf16 lo

__device__ __forceinline__ unsigned fmap(float f) {
    unsigned b = __float_as_uint(f);
    return b ^ ((unsigned)((int)b >> 31) | 0x80000000u);
}
__device__ __forceinline__ uint32_t smem_u32(const void* p) {
    uint32_t a;
    asm("{ .reg .u64 t; cvta.to.shared.u64 t, %1; cvt.u32.u64 %0, t; }" : "=r"(a) : "l"(p));
    return a;
}
__device__ __forceinline__ void mma_bf16(float* c, const uint32_t* a,
                                         uint32_t b0, uint32_t b1) {
    asm volatile(
        "mma.sync.aligned.m16n8k16.row.col.f32.bf16.bf16.f32 "
        "{%0,%1,%2,%3}, {%4,%5,%6,%7}, {%8,%9}, {%0,%1,%2,%3};"
        : "+f"(c[0]), "+f"(c[1]), "+f"(c[2]), "+f"(c[3])
        : "r"(a[0]), "r"(a[1]), "r"(a[2]), "r"(a[3]), "r"(b0), "r"(b1));
}
__device__ __forceinline__ void ldsm4(uint32_t* r, uint32_t addr) {
    asm volatile("ldmatrix.sync.aligned.m8n8.x4.shared.b16 {%0,%1,%2,%3}, [%4];"
        : "=r"(r[0]), "=r"(r[1]), "=r"(r[2]), "=r"(r[3]) : "r"(addr));
}

// ------- small prep kernels -------
__global__ void init_kernel() {
    int idx = blockIdx.x * 256 + threadIdx.x;
    if (idx < 2*NN*H) (&g_segout[0][0])[idx] = 0u;
    if (idx < 2*NN)   (&g_deg[0][0])[idx] = 0;
}

__global__ void uv_kernel(const float* __restrict__ pos, const float* __restrict__ W1,
                          const float* __restrict__ bias1, int g) {
    int i = blockIdx.x, ch = threadIdx.x;
    float p0 = pos[i*3+0], p1 = pos[i*3+1], p2 = pos[i*3+2];
    float c = p0*W1[3*H+ch] + p1*W1[4*H+ch] + p2*W1[5*H+ch];
    float a = p0*W1[0*H+ch] + p1*W1[1*H+ch] + p2*W1[2*H+ch] + c + bias1[ch];
    g_a[g][i*H+ch] = a;
    g_c[g][i*H+ch] = c;
}

// W2 bf16 split, transposed to [n][k], chunked over k by 64
__global__ void w2prep_kernel(const float* __restrict__ W2, int g) {
    int idx = blockIdx.x * 256 + threadIdx.x;  // k*256+n
    int k = idx >> 8, n = idx & 255;
    float w = W2[idx];
    __nv_bfloat16 hb = __float2bfloat16(w);
    float hf = __bfloat162float(hb);
    __nv_bfloat16 lb = __float2bfloat16(w - hf);
    int o = (k >> 6)*16384 + n*64 + (k & 63);
    g_w2h[g][o] = *(unsigned short*)&hb;
    g_w2l[g][o] = *(unsigned short*)&lb;
}

__global__ void deg_kernel(const int* __restrict__ ei, int g) {
    int e = blockIdx.x * 256 + threadIdx.x;
    if (e < NE) atomicAdd(&g_deg[g][ei[NE + e]], 1);
}

__global__ void scan_kernel(int g) {
    __shared__ int ss[1024];
    int t = threadIdx.x;
    const int CH = (NN + 1023) / 1024;
    int beg = t * CH, end = beg + CH;
    if (end > NN) end = NN;
    if (beg > NN) beg = NN;
    int s = 0;
    for (int i = beg; i < end; i++) s += g_deg[g][i];
    ss[t] = s;
    __syncthreads();
    for (int off = 1; off < 1024; off <<= 1) {
        int v = (t >= off) ? ss[t-off] : 0;
        __syncthreads();
        ss[t] += v;
        __syncthreads();
    }
    int run = (t == 0) ? 0 : ss[t-1];
    for (int i = beg; i < end; i++) {
        g_offs[g][i] = run; g_cursor[g][i] = run; run += g_deg[g][i];
    }
    if (t == 1023) g_offs[g][NN] = NE;
}

__global__ void dinv_kernel() {
    int idx = blockIdx.x * 256 + threadIdx.x;
    if (idx < 2*NN) {
        int g = idx / NN, i = idx - g*NN;
        g_dinv[g][i] = rsqrtf(1.f + (float)g_deg[g][i]);
    }
}

__global__ void fill_kernel(const int* __restrict__ ei, int g) {
    int e = blockIdx.x * 256 + threadIdx.x;
    if (e < NE) {
        int d = ei[NE + e];
        int p = atomicAdd(&g_cursor[g][d], 1);
        g_ssrc[g][p] = ei[e];
        g_sdst[g][p] = d;
    }
}

// ------- mma.sync pointnet: 128 sorted edges x 256 ch, 3-term bf16 split -------
#define OFF_HH 0
#define OFF_HL 18432
#define OFF_WH 36864
#define OFF_WL 73728
#define OFF_DST 131584
#define PN_SMEM 132096

__global__ __launch_bounds__(512, 1)
void pointnet_mma(const float* __restrict__ b2, int g) {
    extern __shared__ char AB[];
    uint32_t abu = smem_u32(AB);
    int tid = threadIdx.x, lane = tid & 31, wid = tid >> 5;
    int e0 = blockIdx.x * 128;
    int* s_dst = (int*)(AB + OFF_DST);
    if (tid < 128) s_dst[tid] = g_sdst[g][e0 + tid];

    // gather assignment: edge = tid>>2, k quarter = (tid&3)*16
    int ge = tid >> 2, kq = (tid & 3) * 16;
    int esrc = g_ssrc[g][e0 + ge] * 256;
    int edst = g_sdst[g][e0 + ge] * 256;
    const float* __restrict__ Aa = g_a[g];
    const float* __restrict__ Cc = g_c[g];

    // warp tiling: 4 edge-groups x 4 ch-groups; warp tile 32 edges x 64 ch
    int eg = wid >> 2, cg = wid & 3;
    int qrow = lane >> 2;          // 0..7
    int qc = (lane & 3) * 2;       // 0,2,4,6

    // ldmatrix per-lane base addresses
    uint32_t aH = abu + OFF_HH + (uint32_t)(eg*32 + (lane & 15))*144 + (lane >> 4)*16;
    uint32_t aL = aH + (OFF_HL - OFF_HH);
    uint32_t bH = abu + OFF_WH +
        (uint32_t)(cg*64 + (lane >> 4)*8 + (lane & 7))*144 + ((lane >> 3) & 1)*16;
    uint32_t bL = bH + (OFF_WL - OFF_WH);

    float acc[2][8][4];
#pragma unroll
    for (int mt = 0; mt < 2; mt++)
#pragma unroll
        for (int nt = 0; nt < 8; nt++)
#pragma unroll
            for (int j = 0; j < 4; j++) acc[mt][nt][j] = 0.f;

    for (int ck = 0; ck < 4; ck++) {
        // ---- gather + bf16 split into s_hh/s_hl ----
        {
            int k0 = ck*64 + kq;
            float4 av[4], cv[4];
#pragma unroll
            for (int q = 0; q < 4; q++) {
                av[q] = *(const float4*)(Aa + esrc + k0 + q*4);
                cv[q] = *(const float4*)(Cc + edst + k0 + q*4);
            }
            char* ph = AB + OFF_HH + ge*144 + kq*2;
            char* pl = AB + OFF_HL + ge*144 + kq*2;
#pragma unroll
            for (int q = 0; q < 4; q++) {
                float h0 = fmaxf(av[q].x - cv[q].x, 0.f);
                float h1 = fmaxf(av[q].y - cv[q].y, 0.f);
                float h2 = fmaxf(av[q].z - cv[q].z, 0.f);
                float h3 = fmaxf(av[q].w - cv[q].w, 0.f);
                uint32_t hi0, hi1, lo0, lo1;
                asm("cvt.rn.bf16x2.f32 %0, %1, %2;" : "=r"(hi0) : "f"(h1), "f"(h0));
                asm("cvt.rn.bf16x2.f32 %0, %1, %2;" : "=r"(hi1) : "f"(h3), "f"(h2));
                float r0 = h0 - __uint_as_float(hi0 << 16);
                float r1 = h1 - __uint_as_float(hi0 & 0xffff0000u);
                float r2 = h2 - __uint_as_float(hi1 << 16);
                float r3 = h3 - __uint_as_float(hi1 & 0xffff0000u);
                asm("cvt.rn.bf16x2.f32 %0, %1, %2;" : "=r"(lo0) : "f"(r1), "f"(r0));
                asm("cvt.rn.bf16x2.f32 %0, %1, %2;" : "=r"(lo1) : "f"(r3), "f"(r2));
                *(uint32_t*)(ph + q*8)     = hi0;
                *(uint32_t*)(ph + q*8 + 4) = hi1;
                *(uint32_t*)(pl + q*8)     = lo0;
                *(uint32_t*)(pl + q*8 + 4) = lo1;
            }
        }
        // ---- stream W chunk [n][64] hi+lo ----
        {
            const uint4* gh4 = (const uint4*)(g_w2h[g] + ck*16384);
            const uint4* gl4 = (const uint4*)(g_w2l[g] + ck*16384);
#pragma unroll
            for (int i = 0; i < 4; i++) {
                int idx = tid + i*512;
                int row = idx >> 3, q = idx & 7;
                *(uint4*)(AB + OFF_WH + row*144 + q*16) = gh4[idx];
                *(uint4*)(AB + OFF_WL + row*144 + q*16) = gl4[idx];
            }
        }
        __syncthreads();

        // ---- MMA over 4 k-steps of 16 ----
#pragma unroll
        for (int kk = 0; kk < 4; kk++) {
            uint32_t ko = kk*32;
            uint32_t bh[4][4], bl[4][4];
#pragma unroll
            for (int p = 0; p < 4; p++) {
                ldsm4(bh[p], bH + p*(16*144) + ko);
                ldsm4(bl[p], bL + p*(16*144) + ko);
            }
#pragma unroll
            for (int mt = 0; mt < 2; mt++) {
                uint32_t ah[4], al[4];
                ldsm4(ah, aH + mt*(16*144) + ko);
                ldsm4(al, aL + mt*(16*144) + ko);
#pragma unroll
                for (int p = 0; p < 4; p++) {
                    mma_bf16(acc[mt][2*p],   ah, bh[p][0], bh[p][1]);
                    mma_bf16(acc[mt][2*p],   al, bh[p][0], bh[p][1]);
                    mma_bf16(acc[mt][2*p],   ah, bl[p][0], bl[p][1]);
                    mma_bf16(acc[mt][2*p+1], ah, bh[p][2], bh[p][3]);
                    mma_bf16(acc[mt][2*p+1], al, bh[p][2], bh[p][3]);
                    mma_bf16(acc[mt][2*p+1], ah, bl[p][2], bl[p][3]);
                }
            }
        }
        __syncthreads();
    }

    // ---- epilogue: accum -> SMEM buf[128][257] -> segmented max -> atomics ----
    float* buf = (float*)AB;
#pragma unroll
    for (int mt = 0; mt < 2; mt++) {
        int row = eg*32 + mt*16 + qrow;
#pragma unroll
        for (int nt = 0; nt < 8; nt++) {
            int col = cg*64 + nt*8 + qc;
            buf[row*257 + col]       = acc[mt][nt][0];
            buf[row*257 + col + 1]   = acc[mt][nt][1];
            buf[(row+8)*257 + col]   = acc[mt][nt][2];
            buf[(row+8)*257 + col+1] = acc[mt][nt][3];
        }
    }
    __syncthreads();
    {
        unsigned* __restrict__ seg = &g_segout[g][0];
        int gch = tid & 255;
        int ebase = (tid >> 8) * 64;
        float bias = b2[gch];
        int cur = s_dst[ebase];
        float mx = buf[ebase*257 + gch];
        for (int q = 1; q < 64; q++) {
            int d = s_dst[ebase + q];
            float v = buf[(ebase+q)*257 + gch];
            if (d != cur) {
                atomicMax(&seg[cur*256 + gch], fmap(mx + bias));
                cur = d; mx = v;
            } else mx = fmaxf(mx, v);
        }
        atomicMax(&seg[cur*256 + gch], fmap(mx + bias));
    }
}

// ------- remaining pipeline (unchanged) -------
__global__ void decode_kernel() {
    int idx = blockIdx.x * 256 + threadIdx.x;
    if (idx >= 2*NN*H) return;
    int g = idx / (NN*H), rem = idx - g*(NN*H);
    unsigned u = (&g_segout[0][0])[idx];
    float f = (u > 0x80000000u) ? __uint_as_float(u ^ 0x80000000u) : 0.f;
    g_hcat[(rem >> 8)*512 + g*256 + (rem & 255)] = f;
}

__global__ __launch_bounds__(256)
void xw_kernel(const float* __restrict__ Wg, int g) {
    __shared__ float s_a[64*16];
    __shared__ float4 s_b[16*32];
    int tid = threadIdx.x, tx = tid & 31, ty = tid >> 5;
    int row0 = blockIdx.x * 64;
    float acc[8][4];
#pragma unroll
    for (int i = 0; i < 8; i++)
#pragma unroll
        for (int j = 0; j < 4; j++) acc[i][j] = 0.f;
    int lr = tid >> 2, lk = (tid & 3) * 4;
    int ar = row0 + lr; if (ar > NN-1) ar = NN-1;
    const float4* B4 = (const float4*)Wg;
    for (int k0 = 0; k0 < 512; k0 += 16) {
        float4 av = *(const float4*)(g_hcat + ar*512 + k0 + lk);
        float4 bv[2];
#pragma unroll
        for (int q = 0; q < 2; q++) {
            int idx = tid + q*256;
            bv[q] = B4[(k0 + (idx >> 5))*32 + (idx & 31)];
        }
        __syncthreads();
        *(float4*)(s_a + lr*16 + lk) = av;
#pragma unroll
        for (int q = 0; q < 2; q++) s_b[tid + q*256] = bv[q];
        __syncthreads();
#pragma unroll
        for (int kk = 0; kk < 16; kk++) {
            float4 b = s_b[kk*32 + tx];
#pragma unroll
            for (int i = 0; i < 8; i++) {
                float a = s_a[(ty*8 + i)*16 + kk];
                acc[i][0] += a*b.x; acc[i][1] += a*b.y;
                acc[i][2] += a*b.z; acc[i][3] += a*b.w;
            }
        }
    }
#pragma unroll
    for (int i = 0; i < 8; i++) {
        int r = row0 + ty*8 + i;
        if (r < NN)
            *(float4*)(g_xw[g] + r*128 + tx*4) =
                make_float4(acc[i][0], acc[i][1], acc[i][2], acc[i][3]);
    }
}

__global__ void agg_kernel(const float* __restrict__ bias, int g) {
    int i = blockIdx.x, ch = threadIdx.x;
    const float* __restrict__ xw = g_xw[g];
    float di = g_dinv[g][i];
    int beg = g_offs[g][i], end = g_offs[g][i+1];
    float acc = 0.f;
    for (int e = beg; e < end; e++) {
        int s = g_ssrc[g][e];
        acc += xw[s*128 + ch] * g_dinv[g][s];
    }
    float v = di*acc + xw[i*128 + ch]*di*di + bias[ch];
    g_h2[i*256 + g*128 + ch] = fmaxf(v, 0.f);
}

__global__ __launch_bounds__(256)
void c3cls_kernel(const float* __restrict__ Wc, const float* __restrict__ bc,
                  const float* __restrict__ clsW) {
    __shared__ float s_a[64*16];
    __shared__ float4 s_b[16*32];
    __shared__ float red[256];
    int tid = threadIdx.x, tx = tid & 31, ty = tid >> 5;
    int row0 = blockIdx.x * 64;
    float acc[8][4];
#pragma unroll
    for (int i = 0; i < 8; i++)
#pragma unroll
        for (int j = 0; j < 4; j++) acc[i][j] = 0.f;
    int lr = tid >> 2, lk = (tid & 3) * 4;
    int ar = row0 + lr; if (ar > NN-1) ar = NN-1;
    const float4* B4 = (const float4*)Wc;
    for (int k0 = 0; k0 < 256; k0 += 16) {
        float4 av = *(const float4*)(g_h2 + ar*256 + k0 + lk);
        float4 bv[2];
#pragma unroll
        for (int q = 0; q < 2; q++) {
            int idx = tid + q*256;
            bv[q] = B4[(k0 + (idx >> 5))*32 + (idx & 31)];
        }
        __syncthreads();
        *(float4*)(s_a + lr*16 + lk) = av;
#pragma unroll
        for (int q = 0; q < 2; q++) s_b[tid + q*256] = bv[q];
        __syncthreads();
#pragma unroll
        for (int kk = 0; kk < 16; kk++) {
            float4 b = s_b[kk*32 + tx];
#pragma unroll
            for (int i = 0; i < 8; i++) {
                float a = s_a[(ty*8 + i)*16 + kk];
                acc[i][0] += a*b.x; acc[i][1] += a*b.y;
                acc[i][2] += a*b.z; acc[i][3] += a*b.w;
            }
        }
    }
    float sum0 = 0.f, sum1 = 0.f, sum2 = 0.f;
#pragma unroll
    for (int i = 0; i < 8; i++) {
        int r = row0 + ty*8 + i;
        if (r < NN) {
#pragma unroll
            for (int jj = 0; jj < 4; jj++) {
                float v = fmaxf(acc[i][jj] + bc[tx*4 + jj], 0.f);
                const float* w = clsW + (r*128 + tx*4 + jj)*3;
                sum0 += v*w[0]; sum1 += v*w[1]; sum2 += v*w[2];
            }
        }
    }
    float sums[3] = {sum0, sum1, sum2};
#pragma unroll
    for (int r3 = 0; r3 < 3; r3++) {
        red[tid] = sums[r3];
        __syncthreads();
        for (int s = 128; s > 0; s >>= 1) {
            if (tid < s) red[tid] += red[tid + s];
            __syncthreads();
        }
        if (tid == 0) g_partial[blockIdx.x*3 + r3] = red[0];
        __syncthreads();
    }
}

__global__ void final_kernel(const float* __restrict__ clsb, float* __restrict__ out, int nblk) {
    int r = threadIdx.x;
    if (r < 3) {
        double s = (double)clsb[r];
        for (int i = 0; i < nblk; i++) s += (double)g_partial[i*3 + r];
        out[r] = (float)s;
    }
}

extern "C" void kernel_launch(void* const* d_in, const int* in_sizes, int n_in,
                              void* d_out, int out_size) {
    const float *pos[2]={0,0}, *W1[2]={0,0}, *b1[2]={0,0}, *W2[2]={0,0}, *b2[2]={0,0};
    const float *gW[2]={0,0}, *gb[2]={0,0}, *cW=0, *cb=0, *clsW=0, *clsb=0;
    const int *ei[2]={0,0};
    int npos=0, nei=0, nw1=0, n256=0, n64k=0, n128=0;
    for (int i = 0; i < n_in; i++) {
        int sz = in_sizes[i];
        const float* f = (const float*)d_in[i];
        if (sz == 3*NN)            { if (npos<2) pos[npos++] = f; }
        else if (sz == 2*NE)       { if (nei<2)  ei[nei++] = (const int*)d_in[i]; }
        else if (sz == 6*H)        { if (nw1<2)  W1[nw1++] = f; }
        else if (sz == H)          { int j=n256++; if(j==0)b1[0]=f; else if(j==1)b2[0]=f;
                                     else if(j==2)b1[1]=f; else if(j==3)b2[1]=f; }
        else if (sz == H*H)        { int j=n64k++; if(j<2) W2[j]=f; else if(j<4) gW[j-2]=f; }
        else if (sz == H/2)        { int j=n128++; if(j<2) gb[j]=f; else cb=f; }
        else if (sz == H*(H/2))    { cW = f; }
        else if (sz == NN*(H/2)*3) { clsW = f; }
        else if (sz == 3)          { clsb = f; }
    }

    static bool attr_done = false;
    if (!attr_done) {
        cudaFuncSetAttribute(pointnet_mma, cudaFuncAttributeMaxDynamicSharedMemorySize, PN_SMEM);
        attr_done = true;
    }

    init_kernel<<<(2*NN*H + 255)/256, 256>>>();
    for (int g = 0; g < 2; g++) {
        uv_kernel<<<NN, 256>>>(pos[g], W1[g], b1[g], g);
        w2prep_kernel<<<H*H/256, 256>>>(W2[g], g);
        deg_kernel<<<(NE + 255)/256, 256>>>(ei[g], g);
    }
    for (int g = 0; g < 2; g++) {
        scan_kernel<<<1, 1024>>>(g);
        fill_kernel<<<(NE + 255)/256, 256>>>(ei[g], g);
    }
    dinv_kernel<<<(2*NN + 255)/256, 256>>>();
    for (int g = 0; g < 2; g++)
        pointnet_mma<<<NE/128, 512, PN_SMEM>>>(b2[g], g);
    decode_kernel<<<(2*NN*H + 255)/256, 256>>>();
    for (int g = 0; g < 2; g++)
        xw_kernel<<<(NN + 63)/64, 256>>>(gW[g], g);
    for (int g = 0; g < 2; g++)
        agg_kernel<<<NN, 128>>>(gb[g], g);
    int nblk = (NN + 63)/64;
    c3cls_kernel<<<nblk, 256>>>(cW, cb, clsW);
    final_kernel<<<1, 32>>>(clsb, (float*)d_out, nblk);
}

// round 7
// speedup vs baseline: 1.7711x; 1.0069x over previous
#include <cuda_runtime.h>
#include <cuda_bf16.h>
#include <cstdint>

#define NN 20000
#define NE 400000
#define H  256

// ------- static scratch (allocations forbidden) -------
__device__ float    g_a[2][NN*H];
__device__ float    g_c[2][NN*H];
__device__ unsigned g_segout[2][NN*H];   // mapped-uint running max, 0 = empty
__device__ float    g_xw[2][NN*128];
__device__ float    g_h2[NN*256];
__device__ int      g_deg[2][NN];
__device__ int      g_offs[2][NN+1];
__device__ int      g_cursor[2][NN];
__device__ int      g_ssrc[2][NE];
__device__ int      g_sdst[2][NE];
__device__ float    g_dinv[2][NN];
__device__ float    g_partial[1024*3];
__device__ unsigned short g_w2h[2][H*H]; // bf16 hi of W2^T, [chunk][n][64k]
__device__ unsigned short g_w2l[2][H*H]; // bf16 lo

__device__ __forceinline__ unsigned fmap(float f) {
    unsigned b = __float_as_uint(f);
    return b ^ ((unsigned)((int)b >> 31) | 0x80000000u);
}
__device__ __forceinline__ uint32_t smem_u32(const void* p) {
    uint32_t a;
    asm("{ .reg .u64 t; cvta.to.shared.u64 t, %1; cvt.u32.u64 %0, t; }" : "=r"(a) : "l"(p));
    return a;
}
// NOTE: non-volatile — lets ptxas reschedule MMAs to hide HMMA latency
__device__ __forceinline__ void mma_bf16(float* c, const uint32_t* a,
                                         uint32_t b0, uint32_t b1) {
    asm("mma.sync.aligned.m16n8k16.row.col.f32.bf16.bf16.f32 "
        "{%0,%1,%2,%3}, {%4,%5,%6,%7}, {%8,%9}, {%0,%1,%2,%3};"
        : "+f"(c[0]), "+f"(c[1]), "+f"(c[2]), "+f"(c[3])
        : "r"(a[0]), "r"(a[1]), "r"(a[2]), "r"(a[3]), "r"(b0), "r"(b1));
}
__device__ __forceinline__ void ldsm4(uint32_t* r, uint32_t addr) {
    asm volatile("ldmatrix.sync.aligned.m8n8.x4.shared.b16 {%0,%1,%2,%3}, [%4];"
        : "=r"(r[0]), "=r"(r[1]), "=r"(r[2]), "=r"(r[3]) : "r"(addr));
}

// ------- small prep kernels -------
__global__ void init_kernel() {
    int idx = blockIdx.x * 256 + threadIdx.x;
    if (idx < 2*NN*H) (&g_segout[0][0])[idx] = 0u;
    if (idx < 2*NN)   (&g_deg[0][0])[idx] = 0;
}

__global__ void uv_kernel(const float* __restrict__ pos, const float* __restrict__ W1,
                          const float* __restrict__ bias1, int g) {
    int i = blockIdx.x, ch = threadIdx.x;
    float p0 = pos[i*3+0], p1 = pos[i*3+1], p2 = pos[i*3+2];
    float c = p0*W1[3*H+ch] + p1*W1[4*H+ch] + p2*W1[5*H+ch];
    float a = p0*W1[0*H+ch] + p1*W1[1*H+ch] + p2*W1[2*H+ch] + c + bias1[ch];
    g_a[g][i*H+ch] = a;
    g_c[g][i*H+ch] = c;
}

// W2 bf16 split, transposed to [n][k], chunked over k by 64
__global__ void w2prep_kernel(const float* __restrict__ W2, int g) {
    int idx = blockIdx.x * 256 + threadIdx.x;  // k*256+n
    int k = idx >> 8, n = idx & 255;
    float w = W2[idx];
    __nv_bfloat16 hb = __float2bfloat16(w);
    float hf = __bfloat162float(hb);
    __nv_bfloat16 lb = __float2bfloat16(w - hf);
    int o = (k >> 6)*16384 + n*64 + (k & 63);
    g_w2h[g][o] = *(unsigned short*)&hb;
    g_w2l[g][o] = *(unsigned short*)&lb;
}

__global__ void deg_kernel(const int* __restrict__ ei, int g) {
    int e = blockIdx.x * 256 + threadIdx.x;
    if (e < NE) atomicAdd(&g_deg[g][ei[NE + e]], 1);
}

__global__ void scan_kernel(int g) {
    __shared__ int ss[1024];
    int t = threadIdx.x;
    const int CH = (NN + 1023) / 1024;
    int beg = t * CH, end = beg + CH;
    if (end > NN) end = NN;
    if (beg > NN) beg = NN;
    int s = 0;
    for (int i = beg; i < end; i++) s += g_deg[g][i];
    ss[t] = s;
    __syncthreads();
    for (int off = 1; off < 1024; off <<= 1) {
        int v = (t >= off) ? ss[t-off] : 0;
        __syncthreads();
        ss[t] += v;
        __syncthreads();
    }
    int run = (t == 0) ? 0 : ss[t-1];
    for (int i = beg; i < end; i++) {
        g_offs[g][i] = run; g_cursor[g][i] = run; run += g_deg[g][i];
    }
    if (t == 1023) g_offs[g][NN] = NE;
}

__global__ void dinv_kernel() {
    int idx = blockIdx.x * 256 + threadIdx.x;
    if (idx < 2*NN) {
        int g = idx / NN, i = idx - g*NN;
        g_dinv[g][i] = rsqrtf(1.f + (float)g_deg[g][i]);
    }
}

__global__ void fill_kernel(const int* __restrict__ ei, int g) {
    int e = blockIdx.x * 256 + threadIdx.x;
    if (e < NE) {
        int d = ei[NE + e];
        int p = atomicAdd(&g_cursor[g][d], 1);
        g_ssrc[g][p] = ei[e];
        g_sdst[g][p] = d;
    }
}

// ------- mma.sync pointnet: 128 sorted edges x 256 ch, 3-term bf16 split -------
#define OFF_HH 0
#define OFF_HL 18432
#define OFF_WH 36864
#define OFF_WL 73728
#define OFF_DST 131584
#define PN_SMEM 132096

__global__ __launch_bounds__(512, 1)
void pointnet_mma(const float* __restrict__ b2, int g) {
    extern __shared__ char AB[];
    uint32_t abu = smem_u32(AB);
    int tid = threadIdx.x, lane = tid & 31, wid = tid >> 5;
    int e0 = blockIdx.x * 128;
    int* s_dst = (int*)(AB + OFF_DST);
    if (tid < 128) s_dst[tid] = g_sdst[g][e0 + tid];

    // gather assignment: edge = tid>>2, k quarter = (tid&3)*16
    int ge = tid >> 2, kq = (tid & 3) * 16;
    int esrc = g_ssrc[g][e0 + ge] * 256;
    int edst = g_sdst[g][e0 + ge] * 256;
    const float* __restrict__ Aa = g_a[g];
    const float* __restrict__ Cc = g_c[g];

    // warp tiling: 4 edge-groups x 4 ch-groups; warp tile 32 edges x 64 ch
    int eg = wid >> 2, cg = wid & 3;
    int qrow = lane >> 2;          // 0..7
    int qc = (lane & 3) * 2;       // 0,2,4,6

    // ldmatrix per-lane base addresses
    uint32_t aH = abu + OFF_HH + (uint32_t)(eg*32 + (lane & 15))*144 + (lane >> 4)*16;
    uint32_t aL = aH + (OFF_HL - OFF_HH);
    uint32_t bH = abu + OFF_WH +
        (uint32_t)(cg*64 + (lane >> 4)*8 + (lane & 7))*144 + ((lane >> 3) & 1)*16;
    uint32_t bL = bH + (OFF_WL - OFF_WH);

    float acc[2][8][4];
#pragma unroll
    for (int mt = 0; mt < 2; mt++)
#pragma unroll
        for (int nt = 0; nt < 8; nt++)
#pragma unroll
            for (int j = 0; j < 4; j++) acc[mt][nt][j] = 0.f;

    for (int ck = 0; ck < 4; ck++) {
        // ---- gather + bf16 split into s_hh/s_hl ----
        {
            int k0 = ck*64 + kq;
            float4 av[4], cv[4];
#pragma unroll
            for (int q = 0; q < 4; q++) {
                av[q] = *(const float4*)(Aa + esrc + k0 + q*4);
                cv[q] = *(const float4*)(Cc + edst + k0 + q*4);
            }
            char* ph = AB + OFF_HH + ge*144 + kq*2;
            char* pl = AB + OFF_HL + ge*144 + kq*2;
#pragma unroll
            for (int q = 0; q < 4; q++) {
                float h0 = fmaxf(av[q].x - cv[q].x, 0.f);
                float h1 = fmaxf(av[q].y - cv[q].y, 0.f);
                float h2 = fmaxf(av[q].z - cv[q].z, 0.f);
                float h3 = fmaxf(av[q].w - cv[q].w, 0.f);
                uint32_t hi0, hi1, lo0, lo1;
                asm("cvt.rn.bf16x2.f32 %0, %1, %2;" : "=r"(hi0) : "f"(h1), "f"(h0));
                asm("cvt.rn.bf16x2.f32 %0, %1, %2;" : "=r"(hi1) : "f"(h3), "f"(h2));
                float r0 = h0 - __uint_as_float(hi0 << 16);
                float r1 = h1 - __uint_as_float(hi0 & 0xffff0000u);
                float r2 = h2 - __uint_as_float(hi1 << 16);
                float r3 = h3 - __uint_as_float(hi1 & 0xffff0000u);
                asm("cvt.rn.bf16x2.f32 %0, %1, %2;" : "=r"(lo0) : "f"(r1), "f"(r0));
                asm("cvt.rn.bf16x2.f32 %0, %1, %2;" : "=r"(lo1) : "f"(r3), "f"(r2));
                *(uint32_t*)(ph + q*8)     = hi0;
                *(uint32_t*)(ph + q*8 + 4) = hi1;
                *(uint32_t*)(pl + q*8)     = lo0;
                *(uint32_t*)(pl + q*8 + 4) = lo1;
            }
        }
        // ---- stream W chunk [n][64] hi+lo ----
        {
            const uint4* gh4 = (const uint4*)(g_w2h[g] + ck*16384);
            const uint4* gl4 = (const uint4*)(g_w2l[g] + ck*16384);
#pragma unroll
            for (int i = 0; i < 4; i++) {
                int idx = tid + i*512;
                int row = idx >> 3, q = idx & 7;
                *(uint4*)(AB + OFF_WH + row*144 + q*16) = gh4[idx];
                *(uint4*)(AB + OFF_WL + row*144 + q*16) = gl4[idx];
            }
        }
        __syncthreads();

        // ---- MMA over 4 k-steps of 16; three passes, chains broken ----
#pragma unroll
        for (int kk = 0; kk < 4; kk++) {
            uint32_t ko = kk*32;
            uint32_t bh[4][4], bl[4][4];
#pragma unroll
            for (int p = 0; p < 4; p++) {
                ldsm4(bh[p], bH + p*(16*144) + ko);
                ldsm4(bl[p], bL + p*(16*144) + ko);
            }
            // pass 1: A_hi * B_hi  (16 independent MMAs)
#pragma unroll
            for (int mt = 0; mt < 2; mt++) {
                uint32_t ah[4];
                ldsm4(ah, aH + mt*(16*144) + ko);
#pragma unroll
                for (int p = 0; p < 4; p++) {
                    mma_bf16(acc[mt][2*p],   ah, bh[p][0], bh[p][1]);
                    mma_bf16(acc[mt][2*p+1], ah, bh[p][2], bh[p][3]);
                }
            }
            // pass 2: A_lo * B_hi
#pragma unroll
            for (int mt = 0; mt < 2; mt++) {
                uint32_t al[4];
                ldsm4(al, aL + mt*(16*144) + ko);
#pragma unroll
                for (int p = 0; p < 4; p++) {
                    mma_bf16(acc[mt][2*p],   al, bh[p][0], bh[p][1]);
                    mma_bf16(acc[mt][2*p+1], al, bh[p][2], bh[p][3]);
                }
            }
            // pass 3: A_hi * B_lo
#pragma unroll
            for (int mt = 0; mt < 2; mt++) {
                uint32_t ah2[4];
                ldsm4(ah2, aH + mt*(16*144) + ko);
#pragma unroll
                for (int p = 0; p < 4; p++) {
                    mma_bf16(acc[mt][2*p],   ah2, bl[p][0], bl[p][1]);
                    mma_bf16(acc[mt][2*p+1], ah2, bl[p][2], bl[p][3]);
                }
            }
        }
        __syncthreads();
    }

    // ---- epilogue: accum -> SMEM buf[128][257] -> segmented max -> atomics ----
    float* buf = (float*)AB;
#pragma unroll
    for (int mt = 0; mt < 2; mt++) {
        int row = eg*32 + mt*16 + qrow;
#pragma unroll
        for (int nt = 0; nt < 8; nt++) {
            int col = cg*64 + nt*8 + qc;
            buf[row*257 + col]       = acc[mt][nt][0];
            buf[row*257 + col + 1]   = acc[mt][nt][1];
            buf[(row+8)*257 + col]   = acc[mt][nt][2];
            buf[(row+8)*257 + col+1] = acc[mt][nt][3];
        }
    }
    __syncthreads();
    {
        unsigned* __restrict__ seg = &g_segout[g][0];
        int gch = tid & 255;
        int ebase = (tid >> 8) * 64;
        float bias = b2[gch];
        int cur = s_dst[ebase];
        float mx = buf[ebase*257 + gch];
        for (int q = 1; q < 64; q++) {
            int d = s_dst[ebase + q];
            float v = buf[(ebase+q)*257 + gch];
            if (d != cur) {
                atomicMax(&seg[cur*256 + gch], fmap(mx + bias));
                cur = d; mx = v;
            } else mx = fmaxf(mx, v);
        }
        atomicMax(&seg[cur*256 + gch], fmap(mx + bias));
    }
}

// ------- xw = decode(segout) @ gW : [N,512]@[512,128], decode fused -------
__global__ __launch_bounds__(256)
void xw_kernel(const float* __restrict__ Wg, int g) {
    __shared__ float s_a[64*16];
    __shared__ float4 s_b[16*32];
    int tid = threadIdx.x, tx = tid & 31, ty = tid >> 5;
    int row0 = blockIdx.x * 64;
    float acc[8][4];
#pragma unroll
    for (int i = 0; i < 8; i++)
#pragma unroll
        for (int j = 0; j < 4; j++) acc[i][j] = 0.f;
    int lr = tid >> 2, lk = (tid & 3) * 4;
    int ar = row0 + lr; if (ar > NN-1) ar = NN-1;
    const float4* B4 = (const float4*)Wg;
    for (int k0 = 0; k0 < 512; k0 += 16) {
        int kk0 = k0 + lk;
        const unsigned* sp = (kk0 < 256) ? &g_segout[0][ar*256 + kk0]
                                         : &g_segout[1][ar*256 + kk0 - 256];
        uint4 u = *(const uint4*)sp;
        float4 av;
        av.x = (u.x > 0x80000000u) ? __uint_as_float(u.x ^ 0x80000000u) : 0.f;
        av.y = (u.y > 0x80000000u) ? __uint_as_float(u.y ^ 0x80000000u) : 0.f;
        av.z = (u.z > 0x80000000u) ? __uint_as_float(u.z ^ 0x80000000u) : 0.f;
        av.w = (u.w > 0x80000000u) ? __uint_as_float(u.w ^ 0x80000000u) : 0.f;
        float4 bv[2];
#pragma unroll
        for (int q = 0; q < 2; q++) {
            int idx = tid + q*256;
            bv[q] = B4[(k0 + (idx >> 5))*32 + (idx & 31)];
        }
        __syncthreads();
        *(float4*)(s_a + lr*16 + lk) = av;
#pragma unroll
        for (int q = 0; q < 2; q++) s_b[tid + q*256] = bv[q];
        __syncthreads();
#pragma unroll
        for (int kk = 0; kk < 16; kk++) {
            float4 b = s_b[kk*32 + tx];
#pragma unroll
            for (int i = 0; i < 8; i++) {
                float a = s_a[(ty*8 + i)*16 + kk];
                acc[i][0] += a*b.x; acc[i][1] += a*b.y;
                acc[i][2] += a*b.z; acc[i][3] += a*b.w;
            }
        }
    }
#pragma unroll
    for (int i = 0; i < 8; i++) {
        int r = row0 + ty*8 + i;
        if (r < NN)
            *(float4*)(g_xw[g] + r*128 + tx*4) =
                make_float4(acc[i][0], acc[i][1], acc[i][2], acc[i][3]);
    }
}

__global__ void agg_kernel(const float* __restrict__ bias, int g) {
    int i = blockIdx.x, ch = threadIdx.x;
    const float* __restrict__ xw = g_xw[g];
    float di = g_dinv[g][i];
    int beg = g_offs[g][i], end = g_offs[g][i+1];
    float acc = 0.f;
    for (int e = beg; e < end; e++) {
        int s = g_ssrc[g][e];
        acc += xw[s*128 + ch] * g_dinv[g][s];
    }
    float v = di*acc + xw[i*128 + ch]*di*di + bias[ch];
    g_h2[i*256 + g*128 + ch] = fmaxf(v, 0.f);
}

__global__ __launch_bounds__(256)
void c3cls_kernel(const float* __restrict__ Wc, const float* __restrict__ bc,
                  const float* __restrict__ clsW) {
    __shared__ float s_a[64*16];
    __shared__ float4 s_b[16*32];
    __shared__ float red[256];
    int tid = threadIdx.x, tx = tid & 31, ty = tid >> 5;
    int row0 = blockIdx.x * 64;
    float acc[8][4];
#pragma unroll
    for (int i = 0; i < 8; i++)
#pragma unroll
        for (int j = 0; j < 4; j++) acc[i][j] = 0.f;
    int lr = tid >> 2, lk = (tid & 3) * 4;
    int ar = row0 + lr; if (ar > NN-1) ar = NN-1;
    const float4* B4 = (const float4*)Wc;
    for (int k0 = 0; k0 < 256; k0 += 16) {
        float4 av = *(const float4*)(g_h2 + ar*256 + k0 + lk);
        float4 bv[2];
#pragma unroll
        for (int q = 0; q < 2; q++) {
            int idx = tid + q*256;
            bv[q] = B4[(k0 + (idx >> 5))*32 + (idx & 31)];
        }
        __syncthreads();
        *(float4*)(s_a + lr*16 + lk) = av;
#pragma unroll
        for (int q = 0; q < 2; q++) s_b[tid + q*256] = bv[q];
        __syncthreads();
#pragma unroll
        for (int kk = 0; kk < 16; kk++) {
            float4 b = s_b[kk*32 + tx];
#pragma unroll
            for (int i = 0; i < 8; i++) {
                float a = s_a[(ty*8 + i)*16 + kk];
                acc[i][0] += a*b.x; acc[i][1] += a*b.y;
                acc[i][2] += a*b.z; acc[i][3] += a*b.w;
            }
        }
    }
    float sum0 = 0.f, sum1 = 0.f, sum2 = 0.f;
#pragma unroll
    for (int i = 0; i < 8; i++) {
        int r = row0 + ty*8 + i;
        if (r < NN) {
#pragma unroll
            for (int jj = 0; jj < 4; jj++) {
                float v = fmaxf(acc[i][jj] + bc[tx*4 + jj], 0.f);
                const float* w = clsW + (r*128 + tx*4 + jj)*3;
                sum0 += v*w[0]; sum1 += v*w[1]; sum2 += v*w[2];
            }
        }
    }
    float sums[3] = {sum0, sum1, sum2};
#pragma unroll
    for (int r3 = 0; r3 < 3; r3++) {
        red[tid] = sums[r3];
        __syncthreads();
        for (int s = 128; s > 0; s >>= 1) {
            if (tid < s) red[tid] += red[tid + s];
            __syncthreads();
        }
        if (tid == 0) g_partial[blockIdx.x*3 + r3] = red[0];
        __syncthreads();
    }
}

__global__ void final_kernel(const float* __restrict__ clsb, float* __restrict__ out, int nblk) {
    int r = threadIdx.x;
    if (r < 3) {
        double s = (double)clsb[r];
        for (int i = 0; i < nblk; i++) s += (double)g_partial[i*3 + r];
        out[r] = (float)s;
    }
}

extern "C" void kernel_launch(void* const* d_in, const int* in_sizes, int n_in,
                              void* d_out, int out_size) {
    const float *pos[2]={0,0}, *W1[2]={0,0}, *b1[2]={0,0}, *W2[2]={0,0}, *b2[2]={0,0};
    const float *gW[2]={0,0}, *gb[2]={0,0}, *cW=0, *cb=0, *clsW=0, *clsb=0;
    const int *ei[2]={0,0};
    int npos=0, nei=0, nw1=0, n256=0, n64k=0, n128=0;
    for (int i = 0; i < n_in; i++) {
        int sz = in_sizes[i];
        const float* f = (const float*)d_in[i];
        if (sz == 3*NN)            { if (npos<2) pos[npos++] = f; }
        else if (sz == 2*NE)       { if (nei<2)  ei[nei++] = (const int*)d_in[i]; }
        else if (sz == 6*H)        { if (nw1<2)  W1[nw1++] = f; }
        else if (sz == H)          { int j=n256++; if(j==0)b1[0]=f; else if(j==1)b2[0]=f;
                                     else if(j==2)b1[1]=f; else if(j==3)b2[1]=f; }
        else if (sz == H*H)        { int j=n64k++; if(j<2) W2[j]=f; else if(j<4) gW[j-2]=f; }
        else if (sz == H/2)        { int j=n128++; if(j<2) gb[j]=f; else cb=f; }
        else if (sz == H*(H/2))    { cW = f; }
        else if (sz == NN*(H/2)*3) { clsW = f; }
        else if (sz == 3)          { clsb = f; }
    }

    static bool attr_done = false;
    if (!attr_done) {
        cudaFuncSetAttribute(pointnet_mma, cudaFuncAttributeMaxDynamicSharedMemorySize, PN_SMEM);
        attr_done = true;
    }

    init_kernel<<<(2*NN*H + 255)/256, 256>>>();
    for (int g = 0; g < 2; g++) {
        uv_kernel<<<NN, 256>>>(pos[g], W1[g], b1[g], g);
        w2prep_kernel<<<H*H/256, 256>>>(W2[g], g);
        deg_kernel<<<(NE + 255)/256, 256>>>(ei[g], g);
    }
    for (int g = 0; g < 2; g++) {
        scan_kernel<<<1, 1024>>>(g);
        fill_kernel<<<(NE + 255)/256, 256>>>(ei[g], g);
    }
    dinv_kernel<<<(2*NN + 255)/256, 256>>>();
    for (int g = 0; g < 2; g++)
        pointnet_mma<<<NE/128, 512, PN_SMEM>>>(b2[g], g);
    for (int g = 0; g < 2; g++)
        xw_kernel<<<(NN + 63)/64, 256>>>(gW[g], g);
    for (int g = 0; g < 2; g++)
        agg_kernel<<<NN, 128>>>(gb[g], g);
    int nblk = (NN + 63)/64;
    c3cls_kernel<<<nblk, 256>>>(cW, cb, clsW);
    final_kernel<<<1, 32>>>(clsb, (float*)d_out, nblk);
}